// round 5
// baseline (speedup 1.0000x reference)
#include <cuda_runtime.h>

#define NSHAPES 32
#define TPB 256
#define PPT 8           // points per thread (4 float4 loads, 2 float4 stores)

typedef unsigned long long u64;

__device__ __forceinline__ u64 ffma2(u64 a, u64 b, u64 c) {
    u64 d;
    asm("fma.rn.f32x2 %0, %1, %2, %3;" : "=l"(d) : "l"(a), "l"(b), "l"(c));
    return d;
}
__device__ __forceinline__ u64 pack2(float lo, float hi) {
    u64 d;
    asm("mov.b64 %0, {%1, %2};" : "=l"(d) : "f"(lo), "f"(hi));
    return d;
}
__device__ __forceinline__ void unpack2(u64 v, float& lo, float& hi) {
    asm("mov.b64 {%0, %1}, %2;" : "=f"(lo), "=f"(hi) : "l"(v));
}
__device__ __forceinline__ float sqrt_approx(float x) {
    float r;
    asm("sqrt.approx.f32 %0, %1;" : "=f"(r) : "f"(x));
    return r;
}

__global__ __launch_bounds__(TPB)
void multi_rect_sdf_kernel(const float* __restrict__ query,
                           const float* __restrict__ trans,
                           const float* __restrict__ rads,
                           const float* __restrict__ angles,
                           float* __restrict__ out,
                           int npts)
{
    // Per-shape constants, 8 floats (2 x 16B):
    //   [0..3] = (-s, c, -tx, -ty)   -> two u64 pairs for the packed inner fma
    //   [4..7] = ( c, s, -rx, -ry)   -> scalars for outer fma + |.|-r
    __shared__ __align__(16) float shc[NSHAPES * 8];

    const int t = threadIdx.x;
    if (t < NSHAPES) {
        float ang = angles[t];
        float c = cosf(ang), s = sinf(ang);
        float tx = trans[2 * t], ty = trans[2 * t + 1];
        float rx = rads[2 * t],  ry = rads[2 * t + 1];
        float4* v = reinterpret_cast<float4*>(&shc[8 * t]);
        v[0] = make_float4(-s, c, -tx, -ty);
        v[1] = make_float4(c, s, -rx, -ry);
    }
    __syncthreads();

    // Thread t handles PPT consecutive points -> float4-coalesced I/O.
    const int p0 = blockIdx.x * (TPB * PPT) + t * PPT;
    const bool full = (p0 + PPT) <= npts;    // true for every block at N=2M

    // X scalar, Y duplicated-packed (y,y) for the packed inner rotation fma.
    float QX[PPT];
    u64 QYY[PPT];
    if (full) {
#pragma unroll
        for (int h = 0; h < PPT / 2; h++) {
            float4 q = *reinterpret_cast<const float4*>(query + (size_t)p0 * 2 + h * 4);
            QX[2 * h]     = q.x;  QYY[2 * h]     = pack2(q.y, q.y);
            QX[2 * h + 1] = q.z;  QYY[2 * h + 1] = pack2(q.w, q.w);
        }
    } else {
#pragma unroll
        for (int i = 0; i < PPT; i++) {
            int p = p0 + i;
            float x = 0.f, y = 0.f;
            if (p < npts) { x = query[(size_t)p * 2]; y = query[(size_t)p * 2 + 1]; }
            QX[i] = x;
            QYY[i] = pack2(y, y);
        }
    }

    // Single accumulator: E = min over shapes of (sq + min(max(dx,dy),0)).
    // Outside shape: inside-term 0, e = sq >= 0. Inside shape: sq = 0,
    // e = inside <= 0. E<0 => answer E, else sqrt(E). Exact vs reference.
    float E[PPT];
#pragma unroll
    for (int i = 0; i < PPT; i++) E[i] = 3.0e38f;

#pragma unroll 2
    for (int j = 0; j < NSHAPES; j++) {
        const u64* pc = reinterpret_cast<const u64*>(&shc[8 * j]);
        const u64 NSC = pc[0];              // (-s, c)
        const u64 NT  = pc[1];              // (-tx, -ty)
        const float c   = shc[8 * j + 4];
        const float s   = shc[8 * j + 5];
        const float nrx = shc[8 * j + 6];
        const float nry = shc[8 * j + 7];

#pragma unroll
        for (int i = 0; i < PPT; i++) {
            // inner = (-s*y - tx, c*y - ty)  [1 packed fma, FP64 datapath]
            u64 inner = ffma2(NSC, QYY[i], NT);
            float ix, iy;
            unpack2(inner, ix, iy);
            // outer rotation on the fma pipe
            float ax = fmaf(c, QX[i], ix);     // c*x - s*y - tx
            float ay = fmaf(s, QX[i], iy);     // s*x + c*y - ty

            float dx = fabsf(ax) + nrx;        // FADD |.|+(-r)  (fma pipe)
            float dy = fabsf(ay) + nry;
            float mx = fmaxf(dx, 0.f);         // FMNMX          (alu pipe)
            float my = fmaxf(dy, 0.f);
            float ic = fminf(fmaxf(dx, dy), 0.f);
            float e  = fmaf(mx, mx, fmaf(my, my, ic));
            E[i] = fminf(E[i], e);
        }
    }

    if (full) {
#pragma unroll
        for (int h = 0; h < PPT / 4; h++) {
            float4 r;
            float* e4 = &E[4 * h];
            r.x = (e4[0] < 0.f) ? e4[0] : sqrt_approx(e4[0]);
            r.y = (e4[1] < 0.f) ? e4[1] : sqrt_approx(e4[1]);
            r.z = (e4[2] < 0.f) ? e4[2] : sqrt_approx(e4[2]);
            r.w = (e4[3] < 0.f) ? e4[3] : sqrt_approx(e4[3]);
            *reinterpret_cast<float4*>(out + p0 + 4 * h) = r;
        }
    } else {
#pragma unroll
        for (int i = 0; i < PPT; i++) {
            int p = p0 + i;
            if (p < npts)
                out[p] = (E[i] < 0.f) ? E[i] : sqrt_approx(E[i]);
        }
    }
}

extern "C" void kernel_launch(void* const* d_in, const int* in_sizes, int n_in,
                              void* d_out, int out_size)
{
    const float* query  = (const float*)d_in[0];   // (N, 2)
    const float* trans  = (const float*)d_in[1];   // (32, 2)
    const float* rads   = (const float*)d_in[2];   // (32, 2)
    const float* angles = (const float*)d_in[3];   // (32,)
    float* out = (float*)d_out;

    int npts = in_sizes[0] / 2;
    int pts_per_block = TPB * PPT;
    int nblocks = (npts + pts_per_block - 1) / pts_per_block;

    multi_rect_sdf_kernel<<<nblocks, TPB>>>(query, trans, rads, angles, out, npts);
}

// round 7
// speedup vs baseline: 1.0606x; 1.0606x over previous
#include <cuda_runtime.h>

#define NSHAPES 32
#define TPB 256
#define PPT 8           // points per thread (4 float4 loads)

typedef unsigned long long u64;

__device__ __forceinline__ u64 ffma2(u64 a, u64 b, u64 c) {
    u64 d;
    asm("fma.rn.f32x2 %0, %1, %2, %3;" : "=l"(d) : "l"(a), "l"(b), "l"(c));
    return d;
}
__device__ __forceinline__ u64 pack2(float lo, float hi) {
    u64 d;
    asm("mov.b64 %0, {%1, %2};" : "=l"(d) : "f"(lo), "f"(hi));
    return d;
}
__device__ __forceinline__ void unpack2(u64 v, float& lo, float& hi) {
    asm("mov.b64 {%0, %1}, %2;" : "=f"(lo), "=f"(hi) : "l"(v));
}
__device__ __forceinline__ float sqrt_approx(float x) {
    float r;
    asm("sqrt.approx.f32 %0, %1;" : "=f"(r) : "f"(x));
    return r;
}

__global__ __launch_bounds__(TPB)
void multi_rect_sdf_kernel(const float* __restrict__ query,
                           const float* __restrict__ trans,
                           const float* __restrict__ rads,
                           const float* __restrict__ angles,
                           float* __restrict__ out,
                           int npts)
{
    // Per-shape constants, duplicated-packed for direct FFMA2 operands:
    // [0] (c,c) [1] (s,s) [2] (-s,-s) [3] (-tx,-tx) [4] (-ty,-ty) [5] (-rx,-ry)
    __shared__ __align__(16) u64 shc[NSHAPES * 6];

    const int t = threadIdx.x;
    if (t < NSHAPES) {
        float ang = angles[t];
        float c = cosf(ang), s = sinf(ang);
        float tx = trans[2 * t], ty = trans[2 * t + 1];
        float rx = rads[2 * t],  ry = rads[2 * t + 1];
        shc[6 * t + 0] = pack2(c, c);
        shc[6 * t + 1] = pack2(s, s);
        shc[6 * t + 2] = pack2(-s, -s);
        shc[6 * t + 3] = pack2(-tx, -tx);
        shc[6 * t + 4] = pack2(-ty, -ty);
        shc[6 * t + 5] = pack2(-rx, -ry);
    }
    __syncthreads();

    // R2 layout: thread t handles point pairs (base + k*TPB*2 + t*2),
    // k = 0..3 -> fully coalesced float4 loads, lanes pack 2 points.
    const int base = blockIdx.x * (TPB * PPT);
    const bool full = (base + TPB * PPT) <= npts;   // every block at N=2M

    u64 QX[PPT / 2], QY[PPT / 2];   // (x0,x1),(y0,y1) per pair
#pragma unroll
    for (int k = 0; k < PPT / 2; k++) {
        int p = base + k * (TPB * 2) + t * 2;
        if (full || p + 1 < npts) {
            float4 q = *reinterpret_cast<const float4*>(query + (size_t)p * 2);
            QX[k] = pack2(q.x, q.z);
            QY[k] = pack2(q.y, q.w);
        } else {
            QX[k] = pack2(0.f, 0.f);
            QY[k] = pack2(0.f, 0.f);
        }
    }

    // Single accumulator per point: E = min_j (mx^2 + my^2 + min(max(dx,dy),0)).
    // Outside shape: inside-term 0 => e = sq >= 0. Inside: sq = 0 => e <= 0.
    // Negatives always win the min, so E<0 -> E else sqrt(E). Exact.
    float E[PPT];
#pragma unroll
    for (int i = 0; i < PPT; i++) E[i] = 3.0e38f;

    const float* shf = reinterpret_cast<const float*>(shc);  // scalar view

#pragma unroll 4
    for (int j = 0; j < NSHAPES; j++) {
        const u64 C2   = shc[6 * j + 0];
        const u64 S2   = shc[6 * j + 1];
        const u64 NS2  = shc[6 * j + 2];
        const u64 NTX2 = shc[6 * j + 3];
        const u64 NTY2 = shc[6 * j + 4];
        const float nrx = shf[12 * j + 10];   // (-rx)
        const float nry = shf[12 * j + 11];   // (-ry)

#pragma unroll
        for (int k = 0; k < PPT / 2; k++) {
            // Rotation for 2 points at once (4 packed fmas).
            u64 A = ffma2(C2, QX[k], ffma2(NS2, QY[k], NTX2));  // (rx'_0, rx'_1)
            u64 B = ffma2(S2, QX[k], ffma2(C2, QY[k], NTY2));   // (ry'_0, ry'_1)
            float a0, a1, b0, b1;
            unpack2(A, a0, a1);
            unpack2(B, b0, b1);

            // Interleave the two points so fma/alu ops alternate in the stream.
            float dx0 = fabsf(a0) + nrx;            // fma pipe
            float dx1 = fabsf(a1) + nrx;
            float dy0 = fabsf(b0) + nry;
            float dy1 = fabsf(b1) + nry;
            float mx0 = fmaxf(dx0, 0.f);            // alu pipe
            float mx1 = fmaxf(dx1, 0.f);
            float my0 = fmaxf(dy0, 0.f);
            float my1 = fmaxf(dy1, 0.f);
            float ic0 = fminf(fmaxf(dx0, dy0), 0.f);
            float ic1 = fminf(fmaxf(dx1, dy1), 0.f);
            float e0  = fmaf(mx0, mx0, fmaf(my0, my0, ic0));
            float e1  = fmaf(mx1, mx1, fmaf(my1, my1, ic1));
            E[2 * k]     = fminf(E[2 * k],     e0);
            E[2 * k + 1] = fminf(E[2 * k + 1], e1);
        }
    }

#pragma unroll
    for (int k = 0; k < PPT / 2; k++) {
        int p = base + k * (TPB * 2) + t * 2;
        float e0 = E[2 * k], e1 = E[2 * k + 1];
        if (full || p + 1 < npts) {
            float2 r;
            r.x = (e0 < 0.f) ? e0 : sqrt_approx(e0);
            r.y = (e1 < 0.f) ? e1 : sqrt_approx(e1);
            *reinterpret_cast<float2*>(out + p) = r;
        } else if (p < npts) {
            out[p] = (e0 < 0.f) ? e0 : sqrt_approx(e0);
        }
    }
}

extern "C" void kernel_launch(void* const* d_in, const int* in_sizes, int n_in,
                              void* d_out, int out_size)
{
    const float* query  = (const float*)d_in[0];   // (N, 2)
    const float* trans  = (const float*)d_in[1];   // (32, 2)
    const float* rads   = (const float*)d_in[2];   // (32, 2)
    const float* angles = (const float*)d_in[3];   // (32,)
    float* out = (float*)d_out;

    int npts = in_sizes[0] / 2;
    int pts_per_block = TPB * PPT;
    int nblocks = (npts + pts_per_block - 1) / pts_per_block;

    multi_rect_sdf_kernel<<<nblocks, TPB>>>(query, trans, rads, angles, out, npts);
}